// round 2
// baseline (speedup 1.0000x reference)
#include <cuda_runtime.h>
#include <math.h>

// SpatialGRU: 32x32 wavefront scan, B=64, U=64, C=64.
// Per diagonal d (0..62): phase1 = GEMM q@W (+bias) for all cells on the
// diagonal; phase2 = sigmoid/r*hcat, @U_rec, softmax gates, combine, write state.
//
// Scratch lives in __device__ globals (no allocation allowed).

#define BATCH 64
#define UNITS 64
#define NCELL 1024      // 32*32
#define NOUT  448       // 7*UNITS
#define CELLSZ 4096     // 64*64

__device__ float g_x[NCELL * CELLSZ];     // x[t][b][c]  (16 MB)
__device__ float g_xWij[NCELL * CELLSZ];  // x[t] @ W_ij (16 MB)
__device__ float g_S[NCELL * CELLSZ];     // h of cell t (16 MB)
__device__ float g_Z[32 * BATCH * NOUT];  // per-diagonal raw gate pre-acts (3.5 MB)

// ---------------------------------------------------------------------------
// Setup 1: transpose inputs (B,C,32,32) -> g_x[t][b][c]
// grid (32 tTiles, 2 cTiles, 64 b), block (32,32)
// ---------------------------------------------------------------------------
__global__ void k_transpose(const float* __restrict__ in) {
    __shared__ float tile[32][33];
    int b = blockIdx.z;
    int t0 = blockIdx.x * 32;
    int c0 = blockIdx.y * 32;
    int tx = threadIdx.x, ty = threadIdx.y;
    // in[b][c][t] with t = i*32+j contiguous
    tile[ty][tx] = in[b * 65536 + (c0 + ty) * 1024 + t0 + tx];
    __syncthreads();
    g_x[(t0 + ty) * 4096 + b * 64 + c0 + tx] = tile[tx][ty];
}

// ---------------------------------------------------------------------------
// Setup 2: g_xWij[t] = g_x[t] @ W_ij   (64,64)@(64,64) per block
// grid 1024, block 256
// ---------------------------------------------------------------------------
__global__ void k_xwij(const float* __restrict__ Wij) {
    __shared__ float sX[64 * 65];
    __shared__ float sW[64 * 64];
    int t = blockIdx.x, tid = threadIdx.x;
    for (int idx = tid; idx < 4096; idx += 256) {
        int row = idx >> 6, k = idx & 63;
        sX[row * 65 + k] = g_x[t * 4096 + idx];
        sW[idx] = Wij[idx];  // [k][n]
    }
    __syncthreads();
    int r = tid & 63;
    int cb = (tid >> 6) * 16;
    float acc[16];
#pragma unroll
    for (int s = 0; s < 16; ++s) acc[s] = 0.f;
#pragma unroll 8
    for (int k = 0; k < 64; ++k) {
        float a = sX[r * 65 + k];
        const float4* wp = (const float4*)&sW[k * 64 + cb];
        float4 w0 = wp[0], w1 = wp[1], w2 = wp[2], w3 = wp[3];
        acc[0]  += a * w0.x; acc[1]  += a * w0.y; acc[2]  += a * w0.z; acc[3]  += a * w0.w;
        acc[4]  += a * w1.x; acc[5]  += a * w1.y; acc[6]  += a * w1.z; acc[7]  += a * w1.w;
        acc[8]  += a * w2.x; acc[9]  += a * w2.y; acc[10] += a * w2.z; acc[11] += a * w2.w;
        acc[12] += a * w3.x; acc[13] += a * w3.y; acc[14] += a * w3.z; acc[15] += a * w3.w;
    }
    float* o = &g_xWij[t * 4096 + r * 64 + cb];
#pragma unroll
    for (int s = 0; s < 16; ++s) o[s] = acc[s];
}

// ---------------------------------------------------------------------------
// Phase 1: Z = [h_top | h_left | h_diag | x] @ W + bias   for every cell on
// diagonal d. grid (ncells, 7), block 256. Each CTA: 64 rows x 64 cols, K=256.
// ---------------------------------------------------------------------------
__global__ void k_phase1(int d, const float* __restrict__ W,
                         const float* __restrict__ bias) {
    __shared__ float sA[64 * 65];
    __shared__ float sB[64 * 64];
    int i0 = d > 31 ? d - 31 : 0;
    int i = i0 + blockIdx.x;
    int j = d - i;
    int t = i * 32 + j;
    int tid = threadIdx.x;

    const float* srcs[4];
    srcs[0] = (i > 0)          ? &g_S[(t - 32) * 4096] : (const float*)0;  // h_top
    srcs[1] = (j > 0)          ? &g_S[(t - 1)  * 4096] : (const float*)0;  // h_left
    srcs[2] = (i > 0 && j > 0) ? &g_S[(t - 33) * 4096] : (const float*)0;  // h_diag
    srcs[3] = &g_x[t * 4096];                                              // s_ij

    int col0 = blockIdx.y * 64;
    int r = tid & 63;
    int cb = (tid >> 6) * 16;
    float acc[16];
#pragma unroll
    for (int s = 0; s < 16; ++s) acc[s] = 0.f;

    for (int kc = 0; kc < 4; ++kc) {
        const float* src = srcs[kc];
        for (int idx = tid; idx < 4096; idx += 256) {
            int row = idx >> 6, k = idx & 63;
            sA[row * 65 + k] = src ? src[idx] : 0.f;
            sB[idx] = W[(kc * 64 + row) * 448 + col0 + k];  // row==k_local, k==col
        }
        __syncthreads();
#pragma unroll 8
        for (int k = 0; k < 64; ++k) {
            float a = sA[r * 65 + k];
            const float4* bp = (const float4*)&sB[k * 64 + cb];
            float4 b0 = bp[0], b1 = bp[1], b2 = bp[2], b3 = bp[3];
            acc[0]  += a * b0.x; acc[1]  += a * b0.y; acc[2]  += a * b0.z; acc[3]  += a * b0.w;
            acc[4]  += a * b1.x; acc[5]  += a * b1.y; acc[6]  += a * b1.z; acc[7]  += a * b1.w;
            acc[8]  += a * b2.x; acc[9]  += a * b2.y; acc[10] += a * b2.z; acc[11] += a * b2.w;
            acc[12] += a * b3.x; acc[13] += a * b3.y; acc[14] += a * b3.z; acc[15] += a * b3.w;
        }
        __syncthreads();
    }
    float* zp = &g_Z[((int)blockIdx.x * 64 + r) * 448 + col0 + cb];
    const float* bp = &bias[col0 + cb];
#pragma unroll
    for (int s = 0; s < 16; ++s) zp[s] = acc[s] + bp[s];
}

// ---------------------------------------------------------------------------
// Phase 2: per cell, rows rb..rb+15:
//   r = sigmoid(Z[:, :192]);  G = r * [h_left, h_top, h_diag]
//   P = G @ U_rec;  gates = softmax over 4 groups; h = combine; write g_S.
// grid (ncells, 4), block 128.
// ---------------------------------------------------------------------------
__global__ void k_phase2(int d, const float* __restrict__ Urec,
                         const float* __restrict__ bias,
                         float* __restrict__ out) {
    __shared__ float sU[96 * 64];
    __shared__ float sG[16 * 196];
    int i0 = d > 31 ? d - 31 : 0;
    int i = i0 + blockIdx.x;
    int j = d - i;
    int t = i * 32 + j;
    int cell = blockIdx.x;
    int rb = blockIdx.y * 16;
    int tid = threadIdx.x;

    const float* hT = (i > 0)          ? &g_S[(t - 32) * 4096] : (const float*)0;
    const float* hL = (j > 0)          ? &g_S[(t - 1)  * 4096] : (const float*)0;
    const float* hD = (i > 0 && j > 0) ? &g_S[(t - 33) * 4096] : (const float*)0;

    // G = sigmoid(Z[:, :192]) * [h_left | h_top | h_diag]
    for (int idx = tid; idx < 16 * 192; idx += 128) {
        int rr = idx / 192;
        int c  = idx - rr * 192;
        int row = rb + rr;
        float z = g_Z[(cell * 64 + row) * 448 + c];
        float rg = 1.f / (1.f + expf(-z));
        const float* hs = (c < 64) ? hL : ((c < 128) ? hT : hD);
        float hv = hs ? hs[row * 64 + (c & 63)] : 0.f;
        sG[rr * 196 + c] = rg * hv;
    }

    int rr = tid >> 3;
    int n0 = (tid & 7) * 8;
    float acc[8];
#pragma unroll
    for (int s = 0; s < 8; ++s) acc[s] = 0.f;

    for (int kc = 0; kc < 2; ++kc) {
        __syncthreads();  // sG ready (kc=0) / prior sU reads done (kc=1)
        const float4* u4 = (const float4*)(Urec + kc * 96 * 64);
        float4* su4 = (float4*)sU;
        for (int idx = tid; idx < 96 * 64 / 4; idx += 128) su4[idx] = u4[idx];
        __syncthreads();
#pragma unroll 4
        for (int k = 0; k < 96; ++k) {
            float g = sG[rr * 196 + kc * 96 + k];
            const float4* up = (const float4*)&sU[k * 64 + n0];
            float4 u0 = up[0], u1 = up[1];
            acc[0] += g * u0.x; acc[1] += g * u0.y; acc[2] += g * u0.z; acc[3] += g * u0.w;
            acc[4] += g * u1.x; acc[5] += g * u1.y; acc[6] += g * u1.z; acc[7] += g * u1.w;
        }
    }

    int row = rb + rr;
    const float* zrow = &g_Z[(cell * 64 + row) * 448];
    const float* xw = &g_xWij[t * 4096 + row * 64];
    float* sout = &g_S[t * 4096 + row * 64];
#pragma unroll
    for (int s = 0; s < 8; ++s) {
        int k = n0 + s;
        // softmax over groups: zi (192+k), zl (256+k), zt (320+k), zd (384+k)
        float zi_ = zrow[192 + k], zl_ = zrow[256 + k];
        float zt_ = zrow[320 + k], zd_ = zrow[384 + k];
        float m = fmaxf(fmaxf(zi_, zl_), fmaxf(zt_, zd_));
        float ei = expf(zi_ - m), el = expf(zl_ - m);
        float et = expf(zt_ - m), ed = expf(zd_ - m);
        float inv = 1.f / (ei + el + et + ed);
        float hl = hL ? hL[row * 64 + k] : 0.f;
        float ht = hT ? hT[row * 64 + k] : 0.f;
        float hd = hD ? hD[row * 64 + k] : 0.f;
        float hh = tanhf(xw[k] + bias[448 + k] + acc[s]);
        float h = (el * hl + et * ht + ed * hd + ei * hh) * inv;
        sout[k] = h;
        if (t == 1023) out[row * 64 + k] = h;
    }
}

// ---------------------------------------------------------------------------
extern "C" void kernel_launch(void* const* d_in, const int* in_sizes, int n_in,
                              void* d_out, int out_size) {
    const float* in   = (const float*)d_in[0];  // (64,64,32,32)
    const float* W    = (const float*)d_in[1];  // (256,448)
    const float* Urec = (const float*)d_in[2];  // (192,64)
    const float* bias = (const float*)d_in[3];  // (512)
    const float* Wij  = (const float*)d_in[4];  // (64,64)
    float* out = (float*)d_out;                 // (64,64)

    k_transpose<<<dim3(32, 2, 64), dim3(32, 32)>>>(in);
    k_xwij<<<1024, 256>>>(Wij);

    for (int d = 0; d < 63; ++d) {
        int i0 = d > 31 ? d - 31 : 0;
        int i1 = d < 31 ? d : 31;
        int ncells = i1 - i0 + 1;
        k_phase1<<<dim3(ncells, 7), 256>>>(d, W, bias);
        k_phase2<<<dim3(ncells, 4), 128>>>(d, Urec, bias, out);
    }
}

// round 3
// speedup vs baseline: 1.3534x; 1.3534x over previous
#include <cuda_runtime.h>
#include <math.h>

// SpatialGRU 32x32 wavefront, B=64, U=64, C=64.
// R3: single persistent wavefront kernel (224 CTAs = 32 rows x 7 slices),
// weights resident in smem, x-dependent GEMM hoisted out of the recurrence.

#define TPB 256
#define NS  7      // phase1 column slices per row (448 = 7*64)

__device__ float g_x[1024 * 4096];          // x[t][b][c]          (16 MB)
__device__ float g_XZ[1024 * 64 * 448];     // x@W[192:256]+bias   (112 MB)
__device__ float g_xWij[1024 * 4096];       // x@W_ij + b_ij       (16 MB)
__device__ float g_S[1024 * 4096];          // h state per cell    (16 MB)
__device__ float g_Zbuf[32 * 2 * 448 * 64]; // [row][parity][c][r] col-major (14 MB)
__device__ int   g_zdone[32];
__device__ int   g_hdone[32];

// ---------------------------------------------------------------------------
__global__ void k_init() {
    int t = threadIdx.x;
    if (t < 32) { g_zdone[t] = 0; g_hdone[t] = 0; }
}

// ---------------------------------------------------------------------------
// transpose inputs (B,C,32,32) -> g_x[t][b][c]
__global__ void k_transpose(const float* __restrict__ in) {
    __shared__ float tile[32][33];
    int b = blockIdx.z;
    int t0 = blockIdx.x * 32;
    int c0 = blockIdx.y * 32;
    int tx = threadIdx.x, ty = threadIdx.y;
    tile[ty][tx] = in[b * 65536 + (c0 + ty) * 1024 + t0 + tx];
    __syncthreads();
    g_x[(t0 + ty) * 4096 + b * 64 + c0 + tx] = tile[tx][ty];
}

// ---------------------------------------------------------------------------
// Precompute: for every cell t, XZ[t] = x[t]@W[192:256,:] + bias[:448]
//             and xWij[t] = x[t]@W_ij + bias[448:512].
// grid (1024, 8), block 256. ct 0..6 -> 64-col slices of XZ; ct==7 -> xWij.
__global__ void k_pre(const float* __restrict__ W, const float* __restrict__ Wij,
                      const float* __restrict__ bias) {
    __shared__ float sXT[64 * 65];
    __shared__ float sB[64 * 64];
    int t = blockIdx.x, ct = blockIdx.y, tid = threadIdx.x;
    for (int idx = tid; idx < 4096; idx += TPB) {
        int rr = idx >> 6, k = idx & 63;
        sXT[k * 65 + rr] = g_x[t * 4096 + idx];
        int kk = idx >> 6, c = idx & 63;
        sB[idx] = (ct < 7) ? W[(192 + kk) * 448 + ct * 64 + c] : Wij[kk * 64 + c];
    }
    __syncthreads();
    int r = tid & 63;
    int cb = (tid >> 6) << 4;
    const float* bsrc = (ct < 7) ? (bias + ct * 64 + cb) : (bias + 448 + cb);
    float acc[16];
#pragma unroll
    for (int s = 0; s < 16; ++s) acc[s] = bsrc[s];
#pragma unroll 4
    for (int k = 0; k < 64; ++k) {
        float a = sXT[k * 65 + r];
        const float4* bp = (const float4*)&sB[k * 64 + cb];
        float4 b0 = bp[0], b1 = bp[1], b2 = bp[2], b3 = bp[3];
        acc[0]  += a * b0.x; acc[1]  += a * b0.y; acc[2]  += a * b0.z; acc[3]  += a * b0.w;
        acc[4]  += a * b1.x; acc[5]  += a * b1.y; acc[6]  += a * b1.z; acc[7]  += a * b1.w;
        acc[8]  += a * b2.x; acc[9]  += a * b2.y; acc[10] += a * b2.z; acc[11] += a * b2.w;
        acc[12] += a * b3.x; acc[13] += a * b3.y; acc[14] += a * b3.z; acc[15] += a * b3.w;
    }
    float* o = (ct < 7) ? &g_XZ[t * 28672 + r * 448 + ct * 64 + cb]
                        : &g_xWij[t * 4096 + r * 64 + cb];
#pragma unroll
    for (int s = 0; s < 16; ++s) o[s] = acc[s];
}

// ---------------------------------------------------------------------------
// Persistent wavefront scan. grid 224 = 32 rows x 7 slices, block 256.
// smem: sW[192*64] + sAT[192*65] + sU[192*16]  = 111360 bytes.
// Z layout: col-major [c][r] per (row, parity) buffer; read via __ldcg
// (buffers are reused with alternating parity -> L1 would be stale).
extern "C" __global__ void __launch_bounds__(TPB, 2)
k_scan(const float* __restrict__ W, const float* __restrict__ Urec,
       float* __restrict__ out) {
    extern __shared__ float sm[];
    float* sW  = sm;                 // [k][64]  k=0..191 (q-order: top|left|diag)
    float* sAT = sm + 192 * 64;      // [k][r] pad 65
    float* sU  = sAT + 192 * 65;     // [c][16]  c in r-gate order (left|top|diag)

    int bx = blockIdx.x;
    int row = bx / NS, slice = bx - row * NS;
    int tid = threadIdx.x;

    for (int idx = tid; idx < 192 * 64; idx += TPB) {
        int k = idx >> 6, n = idx & 63;
        sW[idx] = W[k * 448 + slice * 64 + n];
    }
    if (slice < 4)
        for (int idx = tid; idx < 192 * 16; idx += TPB) {
            int c = idx >> 4, n = idx & 15;
            sU[idx] = Urec[c * 64 + slice * 16 + n];
        }
    __syncthreads();

    int r = tid & 63;
    int cb = (tid >> 6) << 4;

    for (int j = 0; j < 32; ++j) {
        int t = row * 32 + j;

        // ---- wait for dependencies (h_left own row; h_top/h_diag row-1) ----
        if (tid == 0) {
            if (j > 0)   while (((volatile int*)g_hdone)[row]     < 4 * j)       {}
            if (row > 0) while (((volatile int*)g_hdone)[row - 1] < 4 * (j + 1)) {}
        }
        __syncthreads();

        const float* srcT = (row > 0)          ? &g_S[(t - 32) * 4096] : (const float*)0;
        const float* srcL = (j > 0)            ? &g_S[(t - 1)  * 4096] : (const float*)0;
        const float* srcD = (row > 0 && j > 0) ? &g_S[(t - 33) * 4096] : (const float*)0;

        // ---- load hcat transposed: sAT[k][r], k = [top(0:64)|left(64:128)|diag(128:192)]
        for (int idx = tid; idx < 4096; idx += TPB) {
            int rr = idx >> 6, c = idx & 63;
            sAT[c * 65 + rr]         = srcT ? srcT[idx] : 0.f;
            sAT[(64 + c) * 65 + rr]  = srcL ? srcL[idx] : 0.f;
            sAT[(128 + c) * 65 + rr] = srcD ? srcD[idx] : 0.f;
        }
        __syncthreads();

        // ---- phase1: Z slice = hcat @ sW + XZ (precomputed x-part + bias) ----
        float acc[16];
        {
            const float4* xz4 = (const float4*)&g_XZ[t * 28672 + r * 448 + slice * 64 + cb];
            float4 x0 = xz4[0], x1 = xz4[1], x2 = xz4[2], x3 = xz4[3];
            acc[0] = x0.x; acc[1] = x0.y; acc[2]  = x0.z; acc[3]  = x0.w;
            acc[4] = x1.x; acc[5] = x1.y; acc[6]  = x1.z; acc[7]  = x1.w;
            acc[8] = x2.x; acc[9] = x2.y; acc[10] = x2.z; acc[11] = x2.w;
            acc[12] = x3.x; acc[13] = x3.y; acc[14] = x3.z; acc[15] = x3.w;
        }
#pragma unroll 4
        for (int k = 0; k < 192; ++k) {
            float a = sAT[k * 65 + r];
            const float4* bp = (const float4*)&sW[k * 64 + cb];
            float4 b0 = bp[0], b1 = bp[1], b2 = bp[2], b3 = bp[3];
            acc[0]  += a * b0.x; acc[1]  += a * b0.y; acc[2]  += a * b0.z; acc[3]  += a * b0.w;
            acc[4]  += a * b1.x; acc[5]  += a * b1.y; acc[6]  += a * b1.z; acc[7]  += a * b1.w;
            acc[8]  += a * b2.x; acc[9]  += a * b2.y; acc[10] += a * b2.z; acc[11] += a * b2.w;
            acc[12] += a * b3.x; acc[13] += a * b3.y; acc[14] += a * b3.z; acc[15] += a * b3.w;
        }
        float* zb = &g_Zbuf[(row * 2 + (j & 1)) * 448 * 64];
#pragma unroll
        for (int s = 0; s < 16; ++s) zb[(slice * 64 + cb + s) * 64 + r] = acc[s];
        __threadfence();
        __syncthreads();
        if (tid == 0) atomicAdd(&g_zdone[row], 1);

        // ---- phase2 on slices 0..3 (16 output cols each) ----
        if (slice < 4) {
            if (tid == 0) while (((volatile int*)g_zdone)[row] < NS * (j + 1)) {}
            __syncthreads();

            // G: sAT[perm(c)] *= sigmoid(Z[:,c]); r-gate order is [left|top|diag]
            for (int idx = tid; idx < 12288; idx += TPB) {
                int c = idx >> 6, rr = idx & 63;
                float z = __ldcg(&zb[c * 64 + rr]);
                float sg = 1.f / (1.f + __expf(-z));
                int kp = (c < 64) ? (64 + c) : ((c < 128) ? (c - 64) : c);
                sAT[kp * 65 + rr] *= sg;
            }
            __syncthreads();

            // P = G @ Urec slice (192 x 16), split in r-gate column order
            int n0 = (tid >> 6) << 2;
            float p0 = 0.f, p1 = 0.f, p2 = 0.f, p3 = 0.f;
#pragma unroll 4
            for (int c = 0; c < 64; ++c) {          // left block
                float a = sAT[(64 + c) * 65 + r];
                float4 u = *(const float4*)&sU[c * 16 + n0];
                p0 += a * u.x; p1 += a * u.y; p2 += a * u.z; p3 += a * u.w;
            }
#pragma unroll 4
            for (int c = 64; c < 128; ++c) {        // top block
                float a = sAT[(c - 64) * 65 + r];
                float4 u = *(const float4*)&sU[c * 16 + n0];
                p0 += a * u.x; p1 += a * u.y; p2 += a * u.z; p3 += a * u.w;
            }
#pragma unroll 4
            for (int c = 128; c < 192; ++c) {       // diag block
                float a = sAT[c * 65 + r];
                float4 u = *(const float4*)&sU[c * 16 + n0];
                p0 += a * u.x; p1 += a * u.y; p2 += a * u.z; p3 += a * u.w;
            }

            float pv[4] = {p0, p1, p2, p3};
#pragma unroll
            for (int q = 0; q < 4; ++q) {
                int n = slice * 16 + n0 + q;
                float zi = __ldcg(&zb[(192 + n) * 64 + r]);
                float zl = __ldcg(&zb[(256 + n) * 64 + r]);
                float zt = __ldcg(&zb[(320 + n) * 64 + r]);
                float zd = __ldcg(&zb[(384 + n) * 64 + r]);
                float m = fmaxf(fmaxf(zi, zl), fmaxf(zt, zd));
                float ei = __expf(zi - m), el = __expf(zl - m);
                float et = __expf(zt - m), ed = __expf(zd - m);
                float inv = 1.f / (ei + el + et + ed);
                float hl = srcL ? srcL[r * 64 + n] : 0.f;
                float ht = srcT ? srcT[r * 64 + n] : 0.f;
                float hd = srcD ? srcD[r * 64 + n] : 0.f;
                float pre = g_xWij[t * 4096 + r * 64 + n] + pv[q];
                pre = fminf(fmaxf(pre, -15.f), 15.f);
                float e2 = __expf(2.f * pre);
                float hh = (e2 - 1.f) / (e2 + 1.f);
                float h = (el * hl + et * ht + ed * hd + ei * hh) * inv;
                g_S[t * 4096 + r * 64 + n] = h;
                if (t == 1023) out[r * 64 + n] = h;
            }
            __threadfence();
            __syncthreads();
            if (tid == 0) atomicAdd(&g_hdone[row], 1);
        }
    }
}

// ---------------------------------------------------------------------------
extern "C" void kernel_launch(void* const* d_in, const int* in_sizes, int n_in,
                              void* d_out, int out_size) {
    const float* in   = (const float*)d_in[0];  // (64,64,32,32)
    const float* W    = (const float*)d_in[1];  // (256,448)
    const float* Urec = (const float*)d_in[2];  // (192,64)
    const float* bias = (const float*)d_in[3];  // (512)
    const float* Wij  = (const float*)d_in[4];  // (64,64)
    float* out = (float*)d_out;                 // (64,64)

    static int smem_set = 0;
    if (!smem_set) {
        cudaFuncSetAttribute(k_scan, cudaFuncAttributeMaxDynamicSharedMemorySize,
                             111360);
        smem_set = 1;
    }

    k_init<<<1, 32>>>();
    k_transpose<<<dim3(32, 2, 64), dim3(32, 32)>>>(in);
    k_pre<<<dim3(1024, 8), TPB>>>(W, Wij, bias);
    k_scan<<<32 * NS, TPB, 111360>>>(W, Urec, out);
}